// round 11
// baseline (speedup 1.0000x reference)
#include <cuda_runtime.h>

// 10-qubit, 3-layer state-vector sim, batch 32. One CTA/sample, 256 thr, 4 amps/thr.
// Packed f32x2; spectator bit gated in-register (half-swap butterflies).
// alpha = 5 shfl + 1 reg + 1 spec (qubits 3-8,9); beta = 1 shfl + 1 reg + 1 spec (2,0,1).
// Ring-CNOT (GF(2)-linear) folded into B->A ring-gather; FINAL ring applied as a
// smem gather so the global store is fully coalesced. 7 barriers total.
// Output: float32 real part, (32,1024) row-major.

#define NT 256
#define DIM 1024
#define NGATES 30

typedef unsigned long long u64;

__device__ __forceinline__ u64 pack2(float lo, float hi) {
    u64 r; asm("mov.b64 %0, {%1, %2};" : "=l"(r) : "f"(lo), "f"(hi)); return r;
}
__device__ __forceinline__ void unpack2(float& lo, float& hi, u64 v) {
    asm("mov.b64 {%0, %1}, %2;" : "=f"(lo), "=f"(hi) : "l"(v));
}
__device__ __forceinline__ u64 swap2(u64 v) {
    float lo, hi; unpack2(lo, hi, v); return pack2(hi, lo);
}
__device__ __forceinline__ u64 fma2(u64 a, u64 b, u64 c) {
    u64 d; asm("fma.rn.f32x2 %0, %1, %2, %3;" : "=l"(d) : "l"(a), "l"(b), "l"(c)); return d;
}
__device__ __forceinline__ u64 mul2(u64 a, u64 b) {
    u64 d; asm("mul.rn.f32x2 %0, %1, %2;" : "=l"(d) : "l"(a), "l"(b)); return d;
}

struct cv { u64 x; u64 y; };   // packed complex pair: (re_s0,re_s1), (im_s0,im_s1)

// n = cA*a + cB*b ; coefficient triples {(x0,x1), (-y0,-y1), (y0,y1)}
__device__ __forceinline__ cv cmadd2(const u64* cA, const u64* cB, cv a, cv b) {
    cv n;
    n.x = fma2(cA[0], a.x, fma2(cA[1], a.y, fma2(cB[0], b.x, mul2(cB[1], b.y))));
    n.y = fma2(cA[0], a.y, fma2(cA[2], a.x, fma2(cB[0], b.y, mul2(cB[2], b.x))));
    return n;
}

__device__ __forceinline__ float2 cmulc(float2 a, float2 b) {
    return make_float2(a.x * b.x - a.y * b.y, a.x * b.y + a.y * b.x);
}

// ring(j): bit_i' = b_i^b_{i+1} (i=0..7), b8' = b8^b9^b0, b9' = b9^b0
__device__ __forceinline__ int ring_f(int j) {
    int low = (j ^ (j >> 1)) & 0xFF;
    int b8  = ((j >> 8) ^ (j >> 9) ^ j) & 1;
    int b9  = ((j >> 9) ^ j) & 1;
    return low | (b8 << 8) | (b9 << 9);
}

__device__ __forceinline__ int phys(int j) { return j ^ ((j >> 5) & 31); }

__device__ __forceinline__ u64 shfl2(u64 v, int msk) {
    float lo, hi; unpack2(lo, hi, v);
    lo = __shfl_xor_sync(0xffffffffu, lo, msk);
    hi = __shfl_xor_sync(0xffffffffu, hi, msk);
    return pack2(lo, hi);
}

// butterfly across lane bit msk
__device__ __forceinline__ void bf_sh(cv v[2], const u64 (*gs)[3], int lane, int msk) {
    const bool hi = (lane & msk) != 0;
    const u64* cA = gs[hi ? 3 : 0];
    const u64* cB = gs[hi ? 2 : 1];
    #pragma unroll
    for (int g = 0; g < 2; g++) {
        cv o; o.x = shfl2(v[g].x, msk); o.y = shfl2(v[g].y, msk);
        v[g] = cmadd2(cA, cB, v[g], o);
    }
}
// butterfly across the vector-group axis (reg bit)
__device__ __forceinline__ void bf_reg(cv v[2], const u64 (*gs)[3]) {
    cv n0 = cmadd2(gs[0], gs[1], v[0], v[1]);
    cv n1 = cmadd2(gs[2], gs[3], v[0], v[1]);
    v[0] = n0; v[1] = n1;
}
// butterfly across the packed spectator bit (register-half swap, no comm)
__device__ __forceinline__ void bf_spec(cv v[2], const u64 (*sp)[3]) {
    #pragma unroll
    for (int g = 0; g < 2; g++) {
        cv o; o.x = swap2(v[g].x); o.y = swap2(v[g].y);
        v[g] = cmadd2(sp[0], sp[1], v[g], o);
    }
}

__global__ __launch_bounds__(NT, 2)
void statevec_kernel(const float* __restrict__ X,      // (32,20)
                     const float* __restrict__ W,      // 90
                     const float* __restrict__ B,      // 90
                     float* __restrict__ out)          // (32,1024) f32 = Re(state)
{
    __shared__ float2 buf0[DIM];
    __shared__ float2 buf1[DIM];
    __shared__ u64    gs[NGATES][4][3];      // splat triples per entry
    __shared__ u64    gspec[3][2][2][3];     // [layer][0:alpha q9,1:beta q1][own,part][3]
    __shared__ float2 gsc[NGATES][4];        // scalar entries (layer-0 closed form)

    const int s    = blockIdx.x;
    const int t    = threadIdx.x;
    const int lane = t & 31;
    const int w    = t >> 5;          // 0..7

    if (t < NGATES) {
        const int a0 = t * 3;
        const float phi   = fmaf(X[s * 20 + (a0    ) % 20], W[a0    ], B[a0    ]);
        const float theta = fmaf(X[s * 20 + (a0 + 1) % 20], W[a0 + 1], B[a0 + 1]);
        const float omega = fmaf(X[s * 20 + (a0 + 2) % 20], W[a0 + 2], B[a0 + 2]);

        float stq, ctq;  __sincosf(theta * 0.5f, &stq, &ctq);
        float sp,  cp;   __sincosf((phi + omega) * 0.5f, &sp, &cp);
        float sm,  cm;   __sincosf((phi - omega) * 0.5f, &sm, &cm);

        float2 m[4];
        m[0] = make_float2( cp * ctq, -sp * ctq);   // m00
        m[1] = make_float2(-cm * stq, -sm * stq);   // m01
        m[2] = make_float2( cm * stq, -sm * stq);   // m10
        m[3] = make_float2( cp * ctq,  sp * ctq);   // m11
        #pragma unroll
        for (int e = 0; e < 4; e++) {
            gsc[t][e]   = m[e];
            gs[t][e][0] = pack2( m[e].x,  m[e].x);
            gs[t][e][1] = pack2(-m[e].y, -m[e].y);
            gs[t][e][2] = pack2( m[e].y,  m[e].y);
        }
        const int q = t - (t / 10) * 10;
        const int l = t / 10;
        if (q == 9 || q == 1) {
            const int which = (q == 9) ? 0 : 1;
            // own: half0 = m00, half1 = m11 ; part: half0 = m01, half1 = m10
            gspec[l][which][0][0] = pack2( m[0].x,  m[3].x);
            gspec[l][which][0][1] = pack2(-m[0].y, -m[3].y);
            gspec[l][which][0][2] = pack2( m[0].y,  m[3].y);
            gspec[l][which][1][0] = pack2( m[1].x,  m[2].x);
            gspec[l][which][1][1] = pack2(-m[1].y, -m[2].y);
            gspec[l][which][1][2] = pack2( m[1].y,  m[2].y);
        }
    }
    __syncthreads();                                           // bar 1

    // index bases
    const int jA0 = (w << 7) | (lane << 2);    // k = (kr<<1)|ks at bits 1..0
    const int jB0 = (lane << 3) | w;           // kr'=bit9, ks'=bit8
    const int rb  = ring_f(jA0);               // ring-gather base

    cv v[2];   // v[kr]: halves = spectator bit (alpha: qubit 9; beta: qubit 1)

    #pragma unroll
    for (int l = 0; l < 3; l++) {
        const int g0 = l * 10;

        // ---------- alpha: qubits 3..7 (shfl), 8 (reg), 9 (spectator) ----------
        if (l == 0) {
            // closed form on |0...0>: qubits 3..9 gated analytically; only w==0 nonzero
            if (w == 0) {
                float2 c = make_float2(1.0f, 0.0f);
                #pragma unroll
                for (int i = 0; i < 5; i++)                    // lane bit i -> qubit 7-i
                    c = cmulc(c, gsc[7 - i][((lane >> i) & 1) ? 2 : 0]);
                float2 c0 = cmulc(c, gsc[8][0]);               // kr=0
                float2 c1 = cmulc(c, gsc[8][2]);               // kr=1
                float2 a00 = cmulc(c0, gsc[9][0]);             // ks=0
                float2 a01 = cmulc(c0, gsc[9][2]);             // ks=1
                float2 a10 = cmulc(c1, gsc[9][0]);
                float2 a11 = cmulc(c1, gsc[9][2]);
                v[0].x = pack2(a00.x, a01.x); v[0].y = pack2(a00.y, a01.y);
                v[1].x = pack2(a10.x, a11.x); v[1].y = pack2(a10.y, a11.y);
            } else {
                v[0].x = v[0].y = v[1].x = v[1].y = 0ull;
            }
        } else {
            // ring gather from buf1 (layout-A logical indices through RING)
            float2 a00 = buf1[phys(rb)];            // k=0: kr0 ks0
            float2 a01 = buf1[phys(rb ^ 0x301)];    // k=1: kr0 ks1  (ring_f(1)=0x301)
            float2 a10 = buf1[phys(rb ^ 0x003)];    // k=2: kr1 ks0  (ring_f(2)=3)
            float2 a11 = buf1[phys(rb ^ 0x302)];    // k=3: kr1 ks1
            v[0].x = pack2(a00.x, a01.x); v[0].y = pack2(a00.y, a01.y);
            v[1].x = pack2(a10.x, a11.x); v[1].y = pack2(a10.y, a11.y);

            bf_reg (v, gs[g0 + 8]);                            // qubit 8
            bf_spec(v, gspec[l][0]);                           // qubit 9 (spectator)
            bf_sh(v, gs[g0 + 7], lane, 1);                     // qubit 7
            bf_sh(v, gs[g0 + 6], lane, 2);
            bf_sh(v, gs[g0 + 5], lane, 4);
            bf_sh(v, gs[g0 + 4], lane, 8);
            bf_sh(v, gs[g0 + 3], lane, 16);                    // qubit 3
        }

        // ---- exchange A -> B ----
        {
            float x0, x1, y0, y1;
            unpack2(x0, x1, v[0].x); unpack2(y0, y1, v[0].y);
            buf0[phys(jA0 | 0)] = make_float2(x0, y0);         // kr0 ks0
            buf0[phys(jA0 | 1)] = make_float2(x1, y1);         // kr0 ks1
            unpack2(x0, x1, v[1].x); unpack2(y0, y1, v[1].y);
            buf0[phys(jA0 | 2)] = make_float2(x0, y0);         // kr1 ks0
            buf0[phys(jA0 | 3)] = make_float2(x1, y1);         // kr1 ks1
        }
        __syncthreads();                                       // bars 2,4,6
        {
            float2 b00 = buf0[phys(jB0)];           // kr'0 ks'0
            float2 b01 = buf0[phys(jB0 | 0x100)];   // kr'0 ks'1
            float2 b10 = buf0[phys(jB0 | 0x200)];   // kr'1 ks'0
            float2 b11 = buf0[phys(jB0 | 0x300)];   // kr'1 ks'1
            v[0].x = pack2(b00.x, b01.x); v[0].y = pack2(b00.y, b01.y);
            v[1].x = pack2(b10.x, b11.x); v[1].y = pack2(b10.y, b11.y);
        }

        // ---------- beta: qubit 0 (reg), 1 (spectator), 2 (shfl) ----------
        bf_reg (v, gs[g0 + 0]);                                // qubit 0 (bit9 = kr')
        bf_spec(v, gspec[l][1]);                               // qubit 1 (bit8 = ks')
        bf_sh(v, gs[g0 + 2], lane, 16);                        // qubit 2 (bit7 = lane b4)

        if (l < 2) {
            float x0, x1, y0, y1;
            unpack2(x0, x1, v[0].x); unpack2(y0, y1, v[0].y);
            buf1[phys(jB0)]         = make_float2(x0, y0);
            buf1[phys(jB0 | 0x100)] = make_float2(x1, y1);
            unpack2(x0, x1, v[1].x); unpack2(y0, y1, v[1].y);
            buf1[phys(jB0 | 0x200)] = make_float2(x0, y0);
            buf1[phys(jB0 | 0x300)] = make_float2(x1, y1);
            __syncthreads();                                   // bars 3,5
        }
    }

    // ---- epilogue: stage real parts in smem, apply final ring as a GATHER,
    //      emit fully coalesced global stores. out[m] = a[ring(m)]. ----
    {
        float* fb = (float*)buf0;                  // 1024-float staging buffer
        float x0, x1;
        unpack2(x0, x1, v[0].x);
        fb[phys(jB0)]         = x0;
        fb[phys(jB0 | 0x100)] = x1;
        unpack2(x0, x1, v[1].x);
        fb[phys(jB0 | 0x200)] = x0;
        fb[phys(jB0 | 0x300)] = x1;
        __syncthreads();                                       // bar 7

        const int rt = ring_f(t);
        // ring(256)=0x180, ring(512)=0x300, ring(768)=0x280 (linearity)
        float* o = out + s * DIM;
        o[t]       = fb[phys(rt)];
        o[t + 256] = fb[phys(rt ^ 0x180)];
        o[t + 512] = fb[phys(rt ^ 0x300)];
        o[t + 768] = fb[phys(rt ^ 0x280)];
    }
}

extern "C" void kernel_launch(void* const* d_in, const int* in_sizes, int n_in,
                              void* d_out, int out_size) {
    const float* X = (const float*)d_in[0];   // (32,20)
    const float* W = (const float*)d_in[1];   // 90
    const float* B = (const float*)d_in[2];   // 90
    statevec_kernel<<<32, NT>>>(X, W, B, (float*)d_out);
}

// round 12
// speedup vs baseline: 1.0296x; 1.0296x over previous
#include <cuda_runtime.h>

// 10-qubit, 3-layer state-vector sim, batch 32. TWO samples per CTA (512 thr),
// 256 thr/sample, 4 amps/thr, packed f32x2 with in-register spectator gating.
// alpha = 5 shfl + 1 reg + 1 spec (qubits 3-8,9); beta = 1 shfl + 1 reg + 1 spec.
// Ring-CNOT (GF(2)-linear) folded into B->A ring-gather + coalesced final gather.
// cmadd uses two parallel chains + add (depth 12 vs 16).
// Output: float32 real part, (32,1024) row-major.

#define NT 512
#define DIM 1024
#define NGATES 30

typedef unsigned long long u64;

__device__ __forceinline__ u64 pack2(float lo, float hi) {
    u64 r; asm("mov.b64 %0, {%1, %2};" : "=l"(r) : "f"(lo), "f"(hi)); return r;
}
__device__ __forceinline__ void unpack2(float& lo, float& hi, u64 v) {
    asm("mov.b64 {%0, %1}, %2;" : "=f"(lo), "=f"(hi) : "l"(v));
}
__device__ __forceinline__ u64 swap2(u64 v) {
    float lo, hi; unpack2(lo, hi, v); return pack2(hi, lo);
}
__device__ __forceinline__ u64 fma2(u64 a, u64 b, u64 c) {
    u64 d; asm("fma.rn.f32x2 %0, %1, %2, %3;" : "=l"(d) : "l"(a), "l"(b), "l"(c)); return d;
}
__device__ __forceinline__ u64 mul2(u64 a, u64 b) {
    u64 d; asm("mul.rn.f32x2 %0, %1, %2;" : "=l"(d) : "l"(a), "l"(b)); return d;
}
__device__ __forceinline__ u64 add2(u64 a, u64 b) {
    u64 d; asm("add.rn.f32x2 %0, %1, %2;" : "=l"(d) : "l"(a), "l"(b)); return d;
}

struct cv { u64 x; u64 y; };   // packed complex pair: (re_s0,re_s1), (im_s0,im_s1)

// n = cA*a + cB*b ; triples {(x0,x1), (-y0,-y1), (y0,y1)}; two parallel chains + add
__device__ __forceinline__ cv cmadd2(const u64* cA, const u64* cB, cv a, cv b) {
    cv n;
    u64 px = fma2(cA[0], a.x, mul2(cA[1], a.y));
    u64 qx = fma2(cB[0], b.x, mul2(cB[1], b.y));
    u64 py = fma2(cA[0], a.y, mul2(cA[2], a.x));
    u64 qy = fma2(cB[0], b.y, mul2(cB[2], b.x));
    n.x = add2(px, qx);
    n.y = add2(py, qy);
    return n;
}

__device__ __forceinline__ float2 cmulc(float2 a, float2 b) {
    return make_float2(a.x * b.x - a.y * b.y, a.x * b.y + a.y * b.x);
}

// ring(j): bit_i' = b_i^b_{i+1} (i=0..7), b8' = b8^b9^b0, b9' = b9^b0
__device__ __forceinline__ int ring_f(int j) {
    int low = (j ^ (j >> 1)) & 0xFF;
    int b8  = ((j >> 8) ^ (j >> 9) ^ j) & 1;
    int b9  = ((j >> 9) ^ j) & 1;
    return low | (b8 << 8) | (b9 << 9);
}

__device__ __forceinline__ int phys(int j) { return j ^ ((j >> 5) & 31); }

__device__ __forceinline__ u64 shfl2(u64 v, int msk) {
    float lo, hi; unpack2(lo, hi, v);
    lo = __shfl_xor_sync(0xffffffffu, lo, msk);
    hi = __shfl_xor_sync(0xffffffffu, hi, msk);
    return pack2(lo, hi);
}

__device__ __forceinline__ void bf_sh(cv v[2], const u64 (*gs)[3], int lane, int msk) {
    const bool hi = (lane & msk) != 0;
    const u64* cA = gs[hi ? 3 : 0];
    const u64* cB = gs[hi ? 2 : 1];
    #pragma unroll
    for (int g = 0; g < 2; g++) {
        cv o; o.x = shfl2(v[g].x, msk); o.y = shfl2(v[g].y, msk);
        v[g] = cmadd2(cA, cB, v[g], o);
    }
}
__device__ __forceinline__ void bf_reg(cv v[2], const u64 (*gs)[3]) {
    cv n0 = cmadd2(gs[0], gs[1], v[0], v[1]);
    cv n1 = cmadd2(gs[2], gs[3], v[0], v[1]);
    v[0] = n0; v[1] = n1;
}
__device__ __forceinline__ void bf_spec(cv v[2], const u64 (*sp)[3]) {
    #pragma unroll
    for (int g = 0; g < 2; g++) {
        cv o; o.x = swap2(v[g].x); o.y = swap2(v[g].y);
        v[g] = cmadd2(sp[0], sp[1], v[g], o);
    }
}

__global__ __launch_bounds__(NT, 1)
void statevec_kernel(const float* __restrict__ X,      // (32,20)
                     const float* __restrict__ W,      // 90
                     const float* __restrict__ B,      // 90
                     float* __restrict__ out)          // (32,1024) f32 = Re(state)
{
    __shared__ float2 buf0[2][DIM];
    __shared__ float2 buf1[2][DIM];
    __shared__ u64    gs[2][NGATES][4][3];
    __shared__ u64    gspec[2][3][2][2][3];
    __shared__ float2 gsc[2][NGATES][4];

    const int half = threadIdx.x >> 8;           // which sample in this CTA
    const int t    = threadIdx.x & 255;
    const int s    = (blockIdx.x << 1) | half;
    const int lane = t & 31;
    const int w    = t >> 5;                     // 0..7

    if (t < NGATES) {
        const int a0 = t * 3;
        const float phi   = fmaf(X[s * 20 + (a0    ) % 20], W[a0    ], B[a0    ]);
        const float theta = fmaf(X[s * 20 + (a0 + 1) % 20], W[a0 + 1], B[a0 + 1]);
        const float omega = fmaf(X[s * 20 + (a0 + 2) % 20], W[a0 + 2], B[a0 + 2]);

        float stq, ctq;  __sincosf(theta * 0.5f, &stq, &ctq);
        float sp,  cp;   __sincosf((phi + omega) * 0.5f, &sp, &cp);
        float sm,  cm;   __sincosf((phi - omega) * 0.5f, &sm, &cm);

        float2 m[4];
        m[0] = make_float2( cp * ctq, -sp * ctq);   // m00
        m[1] = make_float2(-cm * stq, -sm * stq);   // m01
        m[2] = make_float2( cm * stq, -sm * stq);   // m10
        m[3] = make_float2( cp * ctq,  sp * ctq);   // m11
        #pragma unroll
        for (int e = 0; e < 4; e++) {
            gsc[half][t][e]   = m[e];
            gs[half][t][e][0] = pack2( m[e].x,  m[e].x);
            gs[half][t][e][1] = pack2(-m[e].y, -m[e].y);
            gs[half][t][e][2] = pack2( m[e].y,  m[e].y);
        }
        const int q = t - (t / 10) * 10;
        const int l = t / 10;
        if (q == 9 || q == 1) {
            const int which = (q == 9) ? 0 : 1;
            gspec[half][l][which][0][0] = pack2( m[0].x,  m[3].x);
            gspec[half][l][which][0][1] = pack2(-m[0].y, -m[3].y);
            gspec[half][l][which][0][2] = pack2( m[0].y,  m[3].y);
            gspec[half][l][which][1][0] = pack2( m[1].x,  m[2].x);
            gspec[half][l][which][1][1] = pack2(-m[1].y, -m[2].y);
            gspec[half][l][which][1][2] = pack2( m[1].y,  m[2].y);
        }
    }
    __syncthreads();                                           // bar 1

    const int jA0 = (w << 7) | (lane << 2);    // k = (kr<<1)|ks at bits 1..0
    const int jB0 = (lane << 3) | w;           // kr'=bit9, ks'=bit8
    const int rb  = ring_f(jA0);

    const u64 (*GS)[4][3]    = gs[half];
    const u64 (*GSP)[2][2][3] = gspec[half];
    const float2 (*GC)[4]    = gsc[half];
    float2* b0 = buf0[half];
    float2* b1 = buf1[half];

    cv v[2];

    #pragma unroll
    for (int l = 0; l < 3; l++) {
        const int g0 = l * 10;

        // ---------- alpha: qubits 3..7 (shfl), 8 (reg), 9 (spectator) ----------
        if (l == 0) {
            if (w == 0) {
                float2 c = make_float2(1.0f, 0.0f);
                #pragma unroll
                for (int i = 0; i < 5; i++)
                    c = cmulc(c, GC[7 - i][((lane >> i) & 1) ? 2 : 0]);
                float2 c0 = cmulc(c, GC[8][0]);
                float2 c1 = cmulc(c, GC[8][2]);
                float2 a00 = cmulc(c0, GC[9][0]);
                float2 a01 = cmulc(c0, GC[9][2]);
                float2 a10 = cmulc(c1, GC[9][0]);
                float2 a11 = cmulc(c1, GC[9][2]);
                v[0].x = pack2(a00.x, a01.x); v[0].y = pack2(a00.y, a01.y);
                v[1].x = pack2(a10.x, a11.x); v[1].y = pack2(a10.y, a11.y);
            } else {
                v[0].x = v[0].y = v[1].x = v[1].y = 0ull;
            }
        } else {
            float2 a00 = b1[phys(rb)];
            float2 a01 = b1[phys(rb ^ 0x301)];
            float2 a10 = b1[phys(rb ^ 0x003)];
            float2 a11 = b1[phys(rb ^ 0x302)];
            v[0].x = pack2(a00.x, a01.x); v[0].y = pack2(a00.y, a01.y);
            v[1].x = pack2(a10.x, a11.x); v[1].y = pack2(a10.y, a11.y);

            bf_reg (v, GS[g0 + 8]);
            bf_spec(v, GSP[l][0]);
            bf_sh(v, GS[g0 + 7], lane, 1);
            bf_sh(v, GS[g0 + 6], lane, 2);
            bf_sh(v, GS[g0 + 5], lane, 4);
            bf_sh(v, GS[g0 + 4], lane, 8);
            bf_sh(v, GS[g0 + 3], lane, 16);
        }

        // ---- exchange A -> B ----
        {
            float x0, x1, y0, y1;
            unpack2(x0, x1, v[0].x); unpack2(y0, y1, v[0].y);
            b0[phys(jA0 | 0)] = make_float2(x0, y0);
            b0[phys(jA0 | 1)] = make_float2(x1, y1);
            unpack2(x0, x1, v[1].x); unpack2(y0, y1, v[1].y);
            b0[phys(jA0 | 2)] = make_float2(x0, y0);
            b0[phys(jA0 | 3)] = make_float2(x1, y1);
        }
        __syncthreads();                                       // bars 2,4,6
        {
            float2 q00 = b0[phys(jB0)];
            float2 q01 = b0[phys(jB0 | 0x100)];
            float2 q10 = b0[phys(jB0 | 0x200)];
            float2 q11 = b0[phys(jB0 | 0x300)];
            v[0].x = pack2(q00.x, q01.x); v[0].y = pack2(q00.y, q01.y);
            v[1].x = pack2(q10.x, q11.x); v[1].y = pack2(q10.y, q11.y);
        }

        // ---------- beta: qubit 0 (reg), 1 (spectator), 2 (shfl) ----------
        bf_reg (v, GS[g0 + 0]);
        bf_spec(v, GSP[l][1]);
        bf_sh(v, GS[g0 + 2], lane, 16);

        if (l < 2) {
            float x0, x1, y0, y1;
            unpack2(x0, x1, v[0].x); unpack2(y0, y1, v[0].y);
            b1[phys(jB0)]         = make_float2(x0, y0);
            b1[phys(jB0 | 0x100)] = make_float2(x1, y1);
            unpack2(x0, x1, v[1].x); unpack2(y0, y1, v[1].y);
            b1[phys(jB0 | 0x200)] = make_float2(x0, y0);
            b1[phys(jB0 | 0x300)] = make_float2(x1, y1);
            __syncthreads();                                   // bars 3,5
        }
    }

    // ---- epilogue: stage reals, apply final ring as gather, coalesced stores ----
    {
        float* fb = (float*)b0;
        float x0, x1;
        unpack2(x0, x1, v[0].x);
        fb[phys(jB0)]         = x0;
        fb[phys(jB0 | 0x100)] = x1;
        unpack2(x0, x1, v[1].x);
        fb[phys(jB0 | 0x200)] = x0;
        fb[phys(jB0 | 0x300)] = x1;
        __syncthreads();                                       // bar 7

        const int rt = ring_f(t);
        float* o = out + s * DIM;
        o[t]       = fb[phys(rt)];
        o[t + 256] = fb[phys(rt ^ 0x180)];   // ring(256)=0x180
        o[t + 512] = fb[phys(rt ^ 0x300)];   // ring(512)=0x300
        o[t + 768] = fb[phys(rt ^ 0x280)];   // ring(768)=0x280
    }
}

extern "C" void kernel_launch(void* const* d_in, const int* in_sizes, int n_in,
                              void* d_out, int out_size) {
    const float* X = (const float*)d_in[0];   // (32,20)
    const float* W = (const float*)d_in[1];   // 90
    const float* B = (const float*)d_in[2];   // 90
    statevec_kernel<<<16, NT>>>(X, W, B, (float*)d_out);
}